// round 3
// baseline (speedup 1.0000x reference)
#include <cuda_runtime.h>

#define NPATCH 2048
#define XSTR 150                     // floats per row of interleaved xy tile (74 pairs)
#define H01_OFF 0                    // 4096 float2: packed (mu1-src, mu2-src)
#define H23_OFF 8192                 // 4096 float2: packed (Ex2-src, Ey2-src)
#define HC_OFF  16384                // region C: xy tile (64*150 floats) aliased with h4 (4096 floats)
#define SMEM_FLOATS (16384 + 9600)
#define SMEM_BYTES (SMEM_FLOATS * 4) // 103,936 B -> 2 CTAs/SM

__device__ float g_loss[NPATCH];

// ---------------------------------------------------------------------------
// Fused kernel: one block per patch; 3 channels processed serially.
// SSIM (separable 11-tap Gaussian, 'same' zero padding) + both MSE sums,
// combined into the per-patch loss directly.
// ---------------------------------------------------------------------------
__global__ __launch_bounds__(256, 2)
void ssim_kernel(const float* __restrict__ Nn, const float* __restrict__ GT,
                 const float* __restrict__ A, const float* __restrict__ G,
                 const float* __restrict__ BG)
{
    extern __shared__ float sm[];
    float2* h01 = (float2*)(sm + H01_OFF);
    float2* h23 = (float2*)(sm + H23_OFF);

    const int t  = threadIdx.x;
    const int bp = blockIdx.x;      // patch index 0..2047
    const int b  = bp >> 6;
    const int p  = bp & 63;
    const int pr = p >> 3;
    const int pc = p & 7;
    const size_t base0 = ((size_t)(b * 3) * 512 + (size_t)pr * 64) * 512 + (size_t)pc * 64;

    // weights: compile-time constants -> FFMA-imm (rt_SMSP = 1)
    const float gwa[11] = {
        0.00102838f, 0.00759876f, 0.03600077f, 0.10936069f, 0.21300554f,
        0.26601172f,
        0.21300554f, 0.10936069f, 0.03600077f, 0.00759876f, 0.00102838f };

    // ---- zero the 5-pair left/right padding columns of the xy tile (once) ----
    for (int z = t; z < 640; z += 256) {
        int r = z / 10, q = z % 10;
        int cp = (q < 5) ? q : (q + 64);       // pair index 0..4 and 69..73
        int o = HC_OFF + r * XSTR + cp * 2;
        sm[o] = 0.f; sm[o + 1] = 0.f;
    }

    float ssum = 0.f, sbg = 0.f, sa = 0.f;

#pragma unroll 1
    for (int ch = 0; ch < 3; ch++) {
        const size_t base = base0 + (size_t)ch * 512 * 512;
        __syncthreads();   // previous channel's h4/xy reads done before reload

        // ---- load both 64x64 tiles, interleaved as (x,y) pairs ----
#pragma unroll
        for (int k = 0; k < 4; k++) {
            int idx = t + 256 * k;                 // 0..1023 float4 slots
            int row = idx >> 4;
            int c4  = (idx & 15) << 2;
            const float4 xv = *(const float4*)(Nn + base + (size_t)row * 512 + c4);
            const float4 yv = *(const float4*)(GT + base + (size_t)row * 512 + c4);
            float2* dst = (float2*)(sm + HC_OFF + row * XSTR + (c4 + 5) * 2);
            dst[0] = make_float2(xv.x, yv.x);
            dst[1] = make_float2(xv.y, yv.y);
            dst[2] = make_float2(xv.z, yv.z);
            dst[3] = make_float2(xv.w, yv.w);
        }
        __syncthreads();

        // ---- horizontal pass: thread owns 16-px strip of row r ----
        {
            const int r  = t & 63;
            const int c0 = (t >> 6) << 4;
            float a0[16], a1[16], a2[16], a3[16], a4[16];
#pragma unroll
            for (int j = 0; j < 16; j++) { a0[j] = a1[j] = a2[j] = a3[j] = a4[j] = 0.f; }

            const float2* src = (const float2*)(sm + HC_OFF + r * XSTR) + c0;
            float2 cur = src[0];
#pragma unroll
            for (int i = 0; i < 26; i++) {
                float2 nxt = (i < 25) ? src[i + 1] : make_float2(0.f, 0.f);
                float xv = cur.x, yv = cur.y;
                float xx = xv * xv, yy = yv * yv, xy = xv * yv;
#pragma unroll
                for (int j = 0; j < 16; j++) {
                    int k = i - j;
                    if (k >= 0 && k < 11) {
                        a0[j] = fmaf(xv, gwa[k], a0[j]);
                        a1[j] = fmaf(yv, gwa[k], a1[j]);
                        a2[j] = fmaf(xx, gwa[k], a2[j]);
                        a3[j] = fmaf(yy, gwa[k], a3[j]);
                        a4[j] = fmaf(xy, gwa[k], a4[j]);
                    }
                }
                cur = nxt;
            }
            // write h01/h23 (column-major, xor-swizzled) — do not touch xy region
#pragma unroll
            for (int j = 0; j < 16; j++) {
                int c = c0 + j;
                int d = (c << 6) + (r ^ (c & 15));
                h01[d] = make_float2(a0[j], a1[j]);
                h23[d] = make_float2(a2[j], a3[j]);
            }
            __syncthreads();   // all xy reads complete before h4 overwrites region C
#pragma unroll
            for (int j = 0; j < 16; j++) {
                int c = c0 + j;
                sm[HC_OFF + (c << 6) + (r ^ (c & 31))] = a4[j];
            }
        }
        __syncthreads();

        // ---- vertical pass + per-pixel SSIM: thread owns 16-row strip of col c ----
        {
            const int c  = t & 63;
            const int r0 = (t >> 6) << 4;
            float b0[16], b1[16], b2[16], b3[16], b4[16];
#pragma unroll
            for (int j = 0; j < 16; j++) { b0[j] = b1[j] = b2[j] = b3[j] = b4[j] = 0.f; }

#pragma unroll
            for (int i = 0; i < 26; i++) {
                int rr = r0 + i - 5;
                if (rr >= 0 && rr < 64) {          // uniform per warp
                    int d = (c << 6) + (rr ^ (c & 15));
                    float2 p01 = h01[d];
                    float2 p23 = h23[d];
                    float v4 = sm[HC_OFF + (c << 6) + (rr ^ (c & 31))];
#pragma unroll
                    for (int j = 0; j < 16; j++) {
                        int k = i - j;
                        if (k >= 0 && k < 11) {
                            b0[j] = fmaf(p01.x, gwa[k], b0[j]);
                            b1[j] = fmaf(p01.y, gwa[k], b1[j]);
                            b2[j] = fmaf(p23.x, gwa[k], b2[j]);
                            b3[j] = fmaf(p23.y, gwa[k], b3[j]);
                            b4[j] = fmaf(v4,    gwa[k], b4[j]);
                        }
                    }
                }
            }

#pragma unroll
            for (int j = 0; j < 16; j++) {
                float mu1 = b0[j], mu2 = b1[j];
                float mu1sq = mu1 * mu1;
                float mu2sq = mu2 * mu2;
                float mu12  = mu1 * mu2;
                float s1  = b2[j] - mu1sq;
                float s2  = b3[j] - mu2sq;
                float s12 = b4[j] - mu12;
                float num = (2.f * mu12 + 1e-4f) * (2.f * s12 + 9e-4f);
                float den = (mu1sq + mu2sq + 1e-4f) * (s1 + s2 + 9e-4f);
                ssum += __fdividef(num, den);
            }
        }

        // ---- fused per-tile MSE sums: (BG-G)^2 and (A-G)^2 ----
#pragma unroll
        for (int k = 0; k < 4; k++) {
            int idx = t + 256 * k;
            int row = idx >> 4;
            int c4  = (idx & 15) << 2;
            size_t off = base + (size_t)row * 512 + c4;
            float4 av = *(const float4*)(A + off);
            float4 gv = *(const float4*)(G + off);
            float4 bv = *(const float4*)(BG + off);
            float d;
            d = bv.x - gv.x; sbg += d * d;
            d = bv.y - gv.y; sbg += d * d;
            d = bv.z - gv.z; sbg += d * d;
            d = bv.w - gv.w; sbg += d * d;
            d = av.x - gv.x; sa += d * d;
            d = av.y - gv.y; sa += d * d;
            d = av.z - gv.z; sa += d * d;
            d = av.w - gv.w; sa += d * d;
        }
    }

    // ---- block reduce (ssum, sbg, sa) and compute per-patch loss ----
#pragma unroll
    for (int o = 16; o; o >>= 1) {
        ssum += __shfl_xor_sync(0xffffffffu, ssum, o);
        sbg  += __shfl_xor_sync(0xffffffffu, sbg,  o);
        sa   += __shfl_xor_sync(0xffffffffu, sa,   o);
    }
    __shared__ float red[24];
    if ((t & 31) == 0) {
        red[(t >> 5)]      = ssum;
        red[(t >> 5) + 8]  = sbg;
        red[(t >> 5) + 16] = sa;
    }
    __syncthreads();
    if (t == 0) {
        float s0 = 0.f, s1 = 0.f, s2 = 0.f;
#pragma unroll
        for (int w = 0; w < 8; w++) { s0 += red[w]; s1 += red[w + 8]; s2 += red[w + 16]; }
        const float inv = 1.f / 12288.f;
        float ssim_mean = s0 * inv;
        float diff = fminf(1.f - ssim_mean, 1.f);
        g_loss[bp] = diff * (s1 * inv) + (1.f - diff) * (s2 * inv);
    }
}

// ---------------------------------------------------------------------------
// Final combine: sum 2048 per-patch losses into the scalar output.
// ---------------------------------------------------------------------------
__global__ __launch_bounds__(256, 1)
void final_kernel(float* __restrict__ out)
{
    const int t = threadIdx.x;
    float acc = 0.f;
#pragma unroll
    for (int k = 0; k < 8; k++) acc += g_loss[t + 256 * k];
#pragma unroll
    for (int o = 16; o; o >>= 1) acc += __shfl_xor_sync(0xffffffffu, acc, o);
    __shared__ float red[8];
    if ((t & 31) == 0) red[t >> 5] = acc;
    __syncthreads();
    if (t == 0) {
        float s = 0.f;
#pragma unroll
        for (int w = 0; w < 8; w++) s += red[w];
        out[0] = s;
    }
}

// ---------------------------------------------------------------------------
extern "C" void kernel_launch(void* const* d_in, const int* in_sizes, int n_in,
                              void* d_out, int out_size)
{
    const float* A  = (const float*)d_in[0];
    const float* Nn = (const float*)d_in[1];
    const float* GT = (const float*)d_in[2];
    const float* G  = (const float*)d_in[3];
    const float* BG = (const float*)d_in[4];

    cudaFuncSetAttribute(ssim_kernel, cudaFuncAttributeMaxDynamicSharedMemorySize, SMEM_BYTES);

    ssim_kernel<<<NPATCH, 256, SMEM_BYTES>>>(Nn, GT, A, G, BG);
    final_kernel<<<1, 256>>>((float*)d_out);
}

// round 4
// speedup vs baseline: 1.2121x; 1.2121x over previous
#include <cuda_runtime.h>

#define NPATCH 2048
#define XSTR 150                     // floats per row of interleaved xy tile (74 pairs)
#define H01_OFF 0                    // 4096 x 8B: packed (mu1-src, mu2-src)
#define H23_OFF 8192                 // 4096 x 8B: packed (Ex2-src, Ey2-src)
#define HC_OFF  16384                // region C: xy tile (64*150 floats) aliased with h4 (4096 floats)
#define SMEM_FLOATS (16384 + 9600)
#define SMEM_BYTES (SMEM_FLOATS * 4) // 103,936 B -> 2 CTAs/SM

__device__ float g_ssim[3 * NPATCH];   // ch-major for coalesced final reduce
__device__ float g_bg[3 * NPATCH];
__device__ float g_a[3 * NPATCH];

// ---- packed f32x2 helpers (sm_100+) ----
__device__ __forceinline__ unsigned long long pack2(float lo, float hi) {
    unsigned long long r;
    asm("mov.b64 %0, {%1, %2};" : "=l"(r) : "f"(lo), "f"(hi));
    return r;
}
__device__ __forceinline__ void unpack2(unsigned long long v, float& lo, float& hi) {
    asm("mov.b64 {%0, %1}, %2;" : "=f"(lo), "=f"(hi) : "l"(v));
}
__device__ __forceinline__ unsigned long long fma2(unsigned long long a, unsigned long long b,
                                                   unsigned long long c) {
    unsigned long long d;
    asm("fma.rn.f32x2 %0, %1, %2, %3;" : "=l"(d) : "l"(a), "l"(b), "l"(c));
    return d;
}
__device__ __forceinline__ unsigned long long mul2(unsigned long long a, unsigned long long b) {
    unsigned long long d;
    asm("mul.rn.f32x2 %0, %1, %2;" : "=l"(d) : "l"(a), "l"(b));
    return d;
}

// symmetric weight access: gw[k] == gw[10-k], keep only 6 packed registers
#define W2(k) W2u[((k) < 6) ? (k) : (10 - (k))]

// ---------------------------------------------------------------------------
// Fused kernel: per-(patch, channel) SSIM partial sum + MSE partial sums.
// Block = 256 threads. Grid = (2048, 3). 2 CTAs/SM.
// ---------------------------------------------------------------------------
__global__ __launch_bounds__(256, 2)
void ssim_kernel(const float* __restrict__ Nn, const float* __restrict__ GT,
                 const float* __restrict__ A, const float* __restrict__ G,
                 const float* __restrict__ BG)
{
    extern __shared__ float sm[];
    unsigned long long* h01 = (unsigned long long*)(sm + H01_OFF);
    unsigned long long* h23 = (unsigned long long*)(sm + H23_OFF);

    const int t  = threadIdx.x;
    const int bp = blockIdx.x;      // patch index 0..2047
    const int ch = blockIdx.y;      // channel 0..2
    const int b  = bp >> 6;
    const int p  = bp & 63;
    const int pr = p >> 3;
    const int pc = p & 7;
    const size_t base = ((size_t)(b * 3 + ch) * 512 + (size_t)pr * 64) * 512 + (size_t)pc * 64;

    const float gwa[11] = {
        0.00102838f, 0.00759876f, 0.03600077f, 0.10936069f, 0.21300554f,
        0.26601172f,
        0.21300554f, 0.10936069f, 0.03600077f, 0.00759876f, 0.00102838f };
    unsigned long long W2u[6];
#pragma unroll
    for (int k = 0; k < 6; k++) W2u[k] = pack2(gwa[k], gwa[k]);

    // ---- zero the 5-pair left/right padding columns of the xy tile ----
    for (int z = t; z < 640; z += 256) {
        int r = z / 10, q = z % 10;
        int cp = (q < 5) ? q : (q + 64);       // pair index 0..4 and 69..73
        int o = HC_OFF + r * XSTR + cp * 2;
        sm[o] = 0.f; sm[o + 1] = 0.f;
    }
    // ---- load both 64x64 tiles, interleaved as (x,y) pairs ----
#pragma unroll
    for (int k = 0; k < 4; k++) {
        int idx = t + 256 * k;                 // 0..1023 float4 slots
        int row = idx >> 4;
        int c4  = (idx & 15) << 2;
        const float4 xv = *(const float4*)(Nn + base + (size_t)row * 512 + c4);
        const float4 yv = *(const float4*)(GT + base + (size_t)row * 512 + c4);
        float2* dst = (float2*)(sm + HC_OFF + row * XSTR + (c4 + 5) * 2);
        dst[0] = make_float2(xv.x, yv.x);
        dst[1] = make_float2(xv.y, yv.y);
        dst[2] = make_float2(xv.z, yv.z);
        dst[3] = make_float2(xv.w, yv.w);
    }
    __syncthreads();

    // ---- horizontal pass: thread owns 16-px strip of row r, in two 8-px phases ----
    {
        const int r   = t & 63;
        const int c0f = (t >> 6) << 4;
        float A4all[16];                       // xy-plane results, written after sync
#pragma unroll
        for (int ph = 0; ph < 2; ph++) {
            const int c0 = c0f + ph * 8;
            unsigned long long A01[8], A23[8];
            float A4[8];
#pragma unroll
            for (int j = 0; j < 8; j++) { A01[j] = 0ull; A23[j] = 0ull; A4[j] = 0.f; }

#pragma unroll
            for (int i = 0; i < 18; i++) {
                unsigned long long pxy =
                    *(const unsigned long long*)(sm + HC_OFF + r * XSTR + (c0 + i) * 2);
                unsigned long long pxx = mul2(pxy, pxy);
                float xv, yv; unpack2(pxy, xv, yv);
                float sxy = xv * yv;
#pragma unroll
                for (int j = 0; j < 8; j++) {
                    int k = i - j;
                    if (k >= 0 && k < 11) {
                        A01[j] = fma2(pxy, W2(k), A01[j]);
                        A23[j] = fma2(pxx, W2(k), A23[j]);
                        A4[j]  = fmaf(sxy, gwa[k], A4[j]);
                    }
                }
            }
#pragma unroll
            for (int j = 0; j < 8; j++) {
                int c = c0 + j;
                int d = (c << 6) + (r ^ (c & 15));
                h01[d] = A01[j];
                h23[d] = A23[j];
                A4all[ph * 8 + j] = A4[j];
            }
        }
        __syncthreads();   // all xy reads complete before h4 overwrites region C
#pragma unroll
        for (int j = 0; j < 16; j++) {
            int c = c0f + j;
            sm[HC_OFF + (c << 6) + (r ^ (c & 31))] = A4all[j];
        }
    }
    __syncthreads();

    // ---- vertical pass + per-pixel SSIM: thread owns 16-row strip of col c ----
    float ssum = 0.f;
    {
        const int c   = t & 63;
        const int r0f = (t >> 6) << 4;
#pragma unroll
        for (int ph = 0; ph < 2; ph++) {
            const int r0 = r0f + ph * 8;
            unsigned long long B01[8], B23[8];
            float B4[8];
#pragma unroll
            for (int j = 0; j < 8; j++) { B01[j] = 0ull; B23[j] = 0ull; B4[j] = 0.f; }

#pragma unroll
            for (int i = 0; i < 18; i++) {
                int rr = r0 + i - 5;
                if (rr >= 0 && rr < 64) {          // uniform per warp
                    int d = (c << 6) + (rr ^ (c & 15));
                    unsigned long long p01 = h01[d];
                    unsigned long long p23 = h23[d];
                    float v4 = sm[HC_OFF + (c << 6) + (rr ^ (c & 31))];
#pragma unroll
                    for (int j = 0; j < 8; j++) {
                        int k = i - j;
                        if (k >= 0 && k < 11) {
                            B01[j] = fma2(p01, W2(k), B01[j]);
                            B23[j] = fma2(p23, W2(k), B23[j]);
                            B4[j]  = fmaf(v4, gwa[k], B4[j]);
                        }
                    }
                }
            }

#pragma unroll
            for (int j = 0; j < 8; j++) {
                float mu1, mu2; unpack2(B01[j], mu1, mu2);
                float ex2, ey2; unpack2(B23[j], ex2, ey2);
                float mu1sq = mu1 * mu1;
                float mu2sq = mu2 * mu2;
                float mu12  = mu1 * mu2;
                float s1  = ex2 - mu1sq;
                float s2  = ey2 - mu2sq;
                float s12 = B4[j] - mu12;
                float num = (2.f * mu12 + 1e-4f) * (2.f * s12 + 9e-4f);
                float den = (mu1sq + mu2sq + 1e-4f) * (s1 + s2 + 9e-4f);
                ssum += __fdividef(num, den);
            }
        }
    }

    // ---- fused per-tile MSE sums: (BG-G)^2 and (A-G)^2 ----
    float sbg = 0.f, sa = 0.f;
#pragma unroll
    for (int k = 0; k < 4; k++) {
        int idx = t + 256 * k;
        int row = idx >> 4;
        int c4  = (idx & 15) << 2;
        size_t off = base + (size_t)row * 512 + c4;
        float4 av = *(const float4*)(A + off);
        float4 gv = *(const float4*)(G + off);
        float4 bv = *(const float4*)(BG + off);
        float d;
        d = bv.x - gv.x; sbg += d * d;
        d = bv.y - gv.y; sbg += d * d;
        d = bv.z - gv.z; sbg += d * d;
        d = bv.w - gv.w; sbg += d * d;
        d = av.x - gv.x; sa += d * d;
        d = av.y - gv.y; sa += d * d;
        d = av.z - gv.z; sa += d * d;
        d = av.w - gv.w; sa += d * d;
    }

    // ---- block reduce (ssum, sbg, sa) ----
#pragma unroll
    for (int o = 16; o; o >>= 1) {
        ssum += __shfl_xor_sync(0xffffffffu, ssum, o);
        sbg  += __shfl_xor_sync(0xffffffffu, sbg,  o);
        sa   += __shfl_xor_sync(0xffffffffu, sa,   o);
    }
    __shared__ float red[24];
    if ((t & 31) == 0) {
        red[(t >> 5)]      = ssum;
        red[(t >> 5) + 8]  = sbg;
        red[(t >> 5) + 16] = sa;
    }
    __syncthreads();
    if (t == 0) {
        float s0 = 0.f, s1 = 0.f, s2 = 0.f;
#pragma unroll
        for (int w = 0; w < 8; w++) { s0 += red[w]; s1 += red[w + 8]; s2 += red[w + 16]; }
        g_ssim[ch * NPATCH + bp] = s0;
        g_bg[ch * NPATCH + bp]   = s1;
        g_a[ch * NPATCH + bp]    = s2;
    }
}

// ---------------------------------------------------------------------------
// Final combine: per-patch loss + total sum (coalesced reads).
// ---------------------------------------------------------------------------
__global__ __launch_bounds__(256, 1)
void final_kernel(float* __restrict__ out)
{
    const int t = threadIdx.x;
    const float inv = 1.f / 12288.f;
    float acc = 0.f;
#pragma unroll
    for (int k = 0; k < 8; k++) {
        int p = t + 256 * k;
        float s  = (g_ssim[p] + g_ssim[NPATCH + p] + g_ssim[2 * NPATCH + p]) * inv;
        float bg = (g_bg[p]   + g_bg[NPATCH + p]   + g_bg[2 * NPATCH + p])   * inv;
        float a  = (g_a[p]    + g_a[NPATCH + p]    + g_a[2 * NPATCH + p])    * inv;
        float diff = fminf(1.f - s, 1.f);
        acc += diff * bg + (1.f - diff) * a;
    }
#pragma unroll
    for (int o = 16; o; o >>= 1) acc += __shfl_xor_sync(0xffffffffu, acc, o);
    __shared__ float red[8];
    if ((t & 31) == 0) red[t >> 5] = acc;
    __syncthreads();
    if (t == 0) {
        float s = 0.f;
#pragma unroll
        for (int w = 0; w < 8; w++) s += red[w];
        out[0] = s;
    }
}

// ---------------------------------------------------------------------------
extern "C" void kernel_launch(void* const* d_in, const int* in_sizes, int n_in,
                              void* d_out, int out_size)
{
    const float* A  = (const float*)d_in[0];
    const float* Nn = (const float*)d_in[1];
    const float* GT = (const float*)d_in[2];
    const float* G  = (const float*)d_in[3];
    const float* BG = (const float*)d_in[4];

    cudaFuncSetAttribute(ssim_kernel, cudaFuncAttributeMaxDynamicSharedMemorySize, SMEM_BYTES);

    ssim_kernel<<<dim3(NPATCH, 3), 256, SMEM_BYTES>>>(Nn, GT, A, G, BG);
    final_kernel<<<1, 256>>>((float*)d_out);
}

// round 5
// speedup vs baseline: 1.3098x; 1.0806x over previous
#include <cuda_runtime.h>

#define NPATCH 2048
#define XSTR 150                      // floats per row of interleaved xy tile (74 pairs)
#define XY_OFF 0                      // xy tile: 64*150 floats = 38400 B
#define HQ_OFF 9600                   // uint2[4096]: (bf16x2(mu1,mu2), bf16x2(x2,y2)) = 32768 B
#define V4_OFF (9600 + 8192)          // float[4096]: Exy plane = 16384 B
#define SMEM_FLOATS (9600 + 8192 + 4096)
#define SMEM_BYTES (SMEM_FLOATS * 4)  // 87552 B -> 2 CTAs/SM

__device__ float g_ssim[3 * NPATCH];  // ch-major for coalesced final reduce
__device__ float g_bg[3 * NPATCH];
__device__ float g_a[3 * NPATCH];

// ---- packed f32x2 helpers (sm_100+) ----
__device__ __forceinline__ unsigned long long pack2(float lo, float hi) {
    unsigned long long r;
    asm("mov.b64 %0, {%1, %2};" : "=l"(r) : "f"(lo), "f"(hi));
    return r;
}
__device__ __forceinline__ void unpack2(unsigned long long v, float& lo, float& hi) {
    asm("mov.b64 {%0, %1}, %2;" : "=f"(lo), "=f"(hi) : "l"(v));
}
__device__ __forceinline__ unsigned long long fma2(unsigned long long a, unsigned long long b,
                                                   unsigned long long c) {
    unsigned long long d;
    asm("fma.rn.f32x2 %0, %1, %2, %3;" : "=l"(d) : "l"(a), "l"(b), "l"(c));
    return d;
}
__device__ __forceinline__ unsigned long long mul2(unsigned long long a, unsigned long long b) {
    unsigned long long d;
    asm("mul.rn.f32x2 %0, %1, %2;" : "=l"(d) : "l"(a), "l"(b));
    return d;
}
// pack two fp32 into bf16x2: hi <- a, lo <- b
__device__ __forceinline__ unsigned int bf16x2_of(float hi, float lo) {
    unsigned int r;
    asm("cvt.rn.bf16x2.f32 %0, %1, %2;" : "=r"(r) : "f"(hi), "f"(lo));
    return r;
}
// exact bf16 -> fp32 expansion
__device__ __forceinline__ float bf_lo(unsigned int v) { return __uint_as_float(v << 16); }
__device__ __forceinline__ float bf_hi(unsigned int v) { return __uint_as_float(v & 0xFFFF0000u); }

// symmetric weight access: gw[k] == gw[10-k], keep only 6 packed registers
#define W2(k) W2u[((k) < 6) ? (k) : (10 - (k))]

// ---------------------------------------------------------------------------
// Fused kernel: per-(patch, channel) SSIM partial sum + MSE partial sums.
// Block = 256 threads. Grid = (2048, 3). 2 CTAs/SM.
// ---------------------------------------------------------------------------
__global__ __launch_bounds__(256, 2)
void ssim_kernel(const float* __restrict__ Nn, const float* __restrict__ GT,
                 const float* __restrict__ A, const float* __restrict__ G,
                 const float* __restrict__ BG)
{
    extern __shared__ float sm[];
    uint2* hq  = (uint2*)(sm + HQ_OFF);
    float* v4p = sm + V4_OFF;

    const int t  = threadIdx.x;
    const int bp = blockIdx.x;      // patch index 0..2047
    const int ch = blockIdx.y;      // channel 0..2
    const int b  = bp >> 6;
    const int p  = bp & 63;
    const int pr = p >> 3;
    const int pc = p & 7;
    const size_t base = ((size_t)(b * 3 + ch) * 512 + (size_t)pr * 64) * 512 + (size_t)pc * 64;

    const float gwa[11] = {
        0.00102838f, 0.00759876f, 0.03600077f, 0.10936069f, 0.21300554f,
        0.26601172f,
        0.21300554f, 0.10936069f, 0.03600077f, 0.00759876f, 0.00102838f };
    unsigned long long W2u[6];
#pragma unroll
    for (int k = 0; k < 6; k++) W2u[k] = pack2(gwa[k], gwa[k]);

    // ---- zero the 5-pair left/right padding columns of the xy tile ----
    for (int z = t; z < 640; z += 256) {
        int r = z / 10, q = z % 10;
        int cp = (q < 5) ? q : (q + 64);       // pair index 0..4 and 69..73
        int o = XY_OFF + r * XSTR + cp * 2;
        sm[o] = 0.f; sm[o + 1] = 0.f;
    }
    // ---- load both 64x64 tiles, interleaved as (x,y) pairs ----
#pragma unroll
    for (int k = 0; k < 4; k++) {
        int idx = t + 256 * k;                 // 0..1023 float4 slots
        int row = idx >> 4;
        int c4  = (idx & 15) << 2;
        const float4 xv = *(const float4*)(Nn + base + (size_t)row * 512 + c4);
        const float4 yv = *(const float4*)(GT + base + (size_t)row * 512 + c4);
        float2* dst = (float2*)(sm + XY_OFF + row * XSTR + (c4 + 5) * 2);
        dst[0] = make_float2(xv.x, yv.x);
        dst[1] = make_float2(xv.y, yv.y);
        dst[2] = make_float2(xv.z, yv.z);
        dst[3] = make_float2(xv.w, yv.w);
    }
    __syncthreads();

    // ---- horizontal pass: thread owns 16-px strip of row r ----
    {
        const int r  = t & 63;
        const int c0 = (t >> 6) << 4;
        unsigned long long A01[16], A23[16];
        float A4[16];
#pragma unroll
        for (int j = 0; j < 16; j++) { A01[j] = 0ull; A23[j] = 0ull; A4[j] = 0.f; }

#pragma unroll
        for (int i = 0; i < 26; i++) {
            unsigned long long pxy =
                *(const unsigned long long*)(sm + XY_OFF + r * XSTR + (c0 + i) * 2);
            unsigned long long pxx = mul2(pxy, pxy);
            float xv, yv; unpack2(pxy, xv, yv);
            float sxy = xv * yv;
#pragma unroll
            for (int j = 0; j < 16; j++) {
                int k = i - j;
                if (k >= 0 && k < 11) {
                    A01[j] = fma2(pxy, W2(k), A01[j]);
                    A23[j] = fma2(pxx, W2(k), A23[j]);
                    A4[j]  = fmaf(sxy, gwa[k], A4[j]);
                }
            }
        }
        // compress (mu1,mu2)->bf16x2, (Ex2,Ey2)->bf16x2; Exy stays fp32
#pragma unroll
        for (int j = 0; j < 16; j++) {
            int c = c0 + j;
            float m1, m2, x2, y2;
            unpack2(A01[j], m1, m2);
            unpack2(A23[j], x2, y2);
            hq[(c << 6) + (r ^ (c & 15))] =
                make_uint2(bf16x2_of(m2, m1), bf16x2_of(y2, x2));
            v4p[(c << 6) + (r ^ (c & 31))] = A4[j];
        }
    }
    __syncthreads();

    // ---- vertical pass + per-pixel SSIM: thread owns 16-row strip of col c ----
    float ssum = 0.f;
    {
        const int c  = t & 63;
        const int r0 = (t >> 6) << 4;
        unsigned long long B01[16], B23[16];
        float B4[16];
#pragma unroll
        for (int j = 0; j < 16; j++) { B01[j] = 0ull; B23[j] = 0ull; B4[j] = 0.f; }

#pragma unroll
        for (int i = 0; i < 26; i++) {
            int rr = r0 + i - 5;
            if (rr >= 0 && rr < 64) {          // uniform per warp
                uint2 q = hq[(c << 6) + (rr ^ (c & 15))];
                float v4 = v4p[(c << 6) + (rr ^ (c & 31))];
                unsigned long long p01 = pack2(bf_lo(q.x), bf_hi(q.x));
                unsigned long long p23 = pack2(bf_lo(q.y), bf_hi(q.y));
#pragma unroll
                for (int j = 0; j < 16; j++) {
                    int k = i - j;
                    if (k >= 0 && k < 11) {
                        B01[j] = fma2(p01, W2(k), B01[j]);
                        B23[j] = fma2(p23, W2(k), B23[j]);
                        B4[j]  = fmaf(v4, gwa[k], B4[j]);
                    }
                }
            }
        }

#pragma unroll
        for (int j = 0; j < 16; j++) {
            float mu1, mu2; unpack2(B01[j], mu1, mu2);
            float ex2, ey2; unpack2(B23[j], ex2, ey2);
            float mu1sq = mu1 * mu1;
            float mu2sq = mu2 * mu2;
            float mu12  = mu1 * mu2;
            float s1  = ex2 - mu1sq;
            float s2  = ey2 - mu2sq;
            float s12 = B4[j] - mu12;
            float num = (2.f * mu12 + 1e-4f) * (2.f * s12 + 9e-4f);
            float den = (mu1sq + mu2sq + 1e-4f) * (s1 + s2 + 9e-4f);
            ssum += __fdividef(num, den);
        }
    }

    // ---- fused per-tile MSE sums: (BG-G)^2 and (A-G)^2 ----
    float sbg = 0.f, sa = 0.f;
#pragma unroll
    for (int k = 0; k < 4; k++) {
        int idx = t + 256 * k;
        int row = idx >> 4;
        int c4  = (idx & 15) << 2;
        size_t off = base + (size_t)row * 512 + c4;
        float4 av = *(const float4*)(A + off);
        float4 gv = *(const float4*)(G + off);
        float4 bv = *(const float4*)(BG + off);
        float d;
        d = bv.x - gv.x; sbg += d * d;
        d = bv.y - gv.y; sbg += d * d;
        d = bv.z - gv.z; sbg += d * d;
        d = bv.w - gv.w; sbg += d * d;
        d = av.x - gv.x; sa += d * d;
        d = av.y - gv.y; sa += d * d;
        d = av.z - gv.z; sa += d * d;
        d = av.w - gv.w; sa += d * d;
    }

    // ---- block reduce (ssum, sbg, sa) ----
#pragma unroll
    for (int o = 16; o; o >>= 1) {
        ssum += __shfl_xor_sync(0xffffffffu, ssum, o);
        sbg  += __shfl_xor_sync(0xffffffffu, sbg,  o);
        sa   += __shfl_xor_sync(0xffffffffu, sa,   o);
    }
    __shared__ float red[24];
    if ((t & 31) == 0) {
        red[(t >> 5)]      = ssum;
        red[(t >> 5) + 8]  = sbg;
        red[(t >> 5) + 16] = sa;
    }
    __syncthreads();
    if (t == 0) {
        float s0 = 0.f, s1 = 0.f, s2 = 0.f;
#pragma unroll
        for (int w = 0; w < 8; w++) { s0 += red[w]; s1 += red[w + 8]; s2 += red[w + 16]; }
        g_ssim[ch * NPATCH + bp] = s0;
        g_bg[ch * NPATCH + bp]   = s1;
        g_a[ch * NPATCH + bp]    = s2;
    }
}

// ---------------------------------------------------------------------------
// Final combine: per-patch loss + total sum (coalesced reads).
// ---------------------------------------------------------------------------
__global__ __launch_bounds__(256, 1)
void final_kernel(float* __restrict__ out)
{
    const int t = threadIdx.x;
    const float inv = 1.f / 12288.f;
    float acc = 0.f;
#pragma unroll
    for (int k = 0; k < 8; k++) {
        int p = t + 256 * k;
        float s  = (g_ssim[p] + g_ssim[NPATCH + p] + g_ssim[2 * NPATCH + p]) * inv;
        float bg = (g_bg[p]   + g_bg[NPATCH + p]   + g_bg[2 * NPATCH + p])   * inv;
        float a  = (g_a[p]    + g_a[NPATCH + p]    + g_a[2 * NPATCH + p])    * inv;
        float diff = fminf(1.f - s, 1.f);
        acc += diff * bg + (1.f - diff) * a;
    }
#pragma unroll
    for (int o = 16; o; o >>= 1) acc += __shfl_xor_sync(0xffffffffu, acc, o);
    __shared__ float red[8];
    if ((t & 31) == 0) red[t >> 5] = acc;
    __syncthreads();
    if (t == 0) {
        float s = 0.f;
#pragma unroll
        for (int w = 0; w < 8; w++) s += red[w];
        out[0] = s;
    }
}

// ---------------------------------------------------------------------------
extern "C" void kernel_launch(void* const* d_in, const int* in_sizes, int n_in,
                              void* d_out, int out_size)
{
    const float* A  = (const float*)d_in[0];
    const float* Nn = (const float*)d_in[1];
    const float* GT = (const float*)d_in[2];
    const float* G  = (const float*)d_in[3];
    const float* BG = (const float*)d_in[4];

    cudaFuncSetAttribute(ssim_kernel, cudaFuncAttributeMaxDynamicSharedMemorySize, SMEM_BYTES);

    ssim_kernel<<<dim3(NPATCH, 3), 256, SMEM_BYTES>>>(Nn, GT, A, G, BG);
    final_kernel<<<1, 256>>>((float*)d_out);
}